// round 17
// baseline (speedup 1.0000x reference)
#include <cuda_runtime.h>
#include <cuda_bf16.h>
#include <cuda_fp16.h>
#include <cstdint>
#include <cstddef>

// ---------------------------------------------------------------------------
// MessagePassing R16: R15 + (1) per-call counting sort of each edge list by
// src>>7 (128-atom bins) -> scatter T reads become L2-local; (2) gi+gh
// transforms merged into one 6-tile launch with combined bias.
// ---------------------------------------------------------------------------

#define MAX_ATOMS 30720
#define WTAB_ROWS 2880     // 1088 bonds | 576 angles | 832 dihedrals | 192 wi | 192 wh
#define MAX_B 40960
#define MAX_A 61440
#define MAX_D 81920
typedef uint32_t u32;

__device__ float g_h [(size_t)MAX_ATOMS * 64];
__device__ float g_a [(size_t)MAX_ATOMS * 64];
__device__ float g_b [(size_t)MAX_ATOMS * 64];
__device__ __half g_T16[(size_t)MAX_ATOMS * 1088];    // 65 MB max
__device__ float g_G  [(size_t)MAX_ATOMS * 384];      // gi rows 0..191 | gh 192..383
__device__ u32 g_Wint [(size_t)WTAB_ROWS * 64];       // interleaved hi/lo
__device__ u32 g_Xint [(size_t)MAX_ATOMS * 64];
__device__ u32 g_XintH[(size_t)MAX_ATOMS * 64];
__device__ float g_bias[384];                         // bi | bh

// edge sort scratch
__device__ int  g_bins[768];
__device__ int  g_cur [768];
__device__ int2 g_eb[MAX_B];  __device__ float g_fb[(size_t)MAX_B * 16];
__device__ int2 g_ea[MAX_A];  __device__ float g_fa[(size_t)MAX_A * 8];
__device__ int2 g_ed[MAX_D];  __device__ float g_fd[(size_t)MAX_D * 12];

// ---------------------------------------------------------------------------
__device__ __forceinline__ void mma16816(float* d, u32 a0, u32 a1, u32 a2, u32 a3,
                                         u32 b0, u32 b1) {
    asm volatile(
        "mma.sync.aligned.m16n8k16.row.col.f32.bf16.bf16.f32 "
        "{%0,%1,%2,%3}, {%4,%5,%6,%7}, {%8,%9}, {%0,%1,%2,%3};"
        : "+f"(d[0]), "+f"(d[1]), "+f"(d[2]), "+f"(d[3])
        : "r"(a0), "r"(a1), "r"(a2), "r"(a3), "r"(b0), "r"(b1));
}

__device__ __forceinline__ u32 pack_bf2(float a, float b) {
    __nv_bfloat162 t = __floats2bfloat162_rn(a, b);
    return *reinterpret_cast<u32*>(&t);
}

__device__ __forceinline__ uint2 split_pair(float a, float b) {
    float ha = __bfloat162float(__float2bfloat16(a));
    float hb = __bfloat162float(__float2bfloat16(b));
    return make_uint2(pack_bf2(a, b), pack_bf2(a - ha, b - hb));
}

// ---------------------------------------------------------------------------
// weights -> interleaved hi/lo; also zero sort bins and build combined bias.
// ---------------------------------------------------------------------------
__global__ void prep_weights_kernel(const float* __restrict__ We, const float* __restrict__ be,
                                    const float* __restrict__ Wa, const float* __restrict__ ba,
                                    const float* __restrict__ Wd, const float* __restrict__ bd,
                                    const float* __restrict__ wi, const float* __restrict__ wh,
                                    const float* __restrict__ bi, const float* __restrict__ bh)
{
    int idx = blockIdx.x * 256 + threadIdx.x;
    if (idx < 768) g_bins[idx] = 0;
    if (idx < 384) g_bias[idx] = (idx < 192) ? bi[idx] : bh[idx - 192];
    if (idx >= WTAB_ROWS * 32) return;
    int row = idx >> 5, q = idx & 31;
    const float* src; int r;
    if      (row < 1024) { src = We; r = row; }
    else if (row < 1088) { src = be; r = row - 1024; }
    else if (row < 1600) { src = Wa; r = row - 1088; }
    else if (row < 1664) { src = ba; r = row - 1600; }
    else if (row < 2432) { src = Wd; r = row - 1664; }
    else if (row < 2496) { src = bd; r = row - 2432; }
    else if (row < 2688) { src = wi; r = row - 2496; }
    else                 { src = wh; r = row - 2688; }
    float2 x = *reinterpret_cast<const float2*>(src + r * 64 + q * 2);
    *reinterpret_cast<uint2*>(&g_Wint[(size_t)row * 64 + q * 2]) = split_pair(x.x, x.y);
}

// ---------------------------------------------------------------------------
__global__ void hist_kernel(const int* __restrict__ bidx, int nb,
                            const int* __restrict__ aidx, int na,
                            const int* __restrict__ didx, int nd)
{
    int i = blockIdx.x * 256 + threadIdx.x;
    if (i < nb) {
        atomicAdd(&g_bins[bidx[2 * i + 1] >> 7], 1);
    } else if (i < nb + na) {
        int e = i - nb;
        atomicAdd(&g_bins[256 + (aidx[2 * e + 1] >> 7)], 1);
    } else if (i < nb + na + nd) {
        int e = i - nb - na;
        atomicAdd(&g_bins[512 + (didx[2 * e + 1] >> 7)], 1);
    }
}

// segmented exclusive scan over 3 x 256 bins -> cursors
__global__ void scan_kernel()
{
    __shared__ int s[768];
    int i = threadIdx.x;
    int c = g_bins[i];
    s[i] = c;
    __syncthreads();
    int lane = i & 255;
    for (int d = 1; d < 256; d <<= 1) {
        int v = (lane >= d) ? s[i - d] : 0;
        __syncthreads();
        s[i] += v;
        __syncthreads();
    }
    g_cur[i] = s[i] - c;   // exclusive within segment
}

template <int KF, int TYPE>
__global__ void permute_kernel(const int* __restrict__ idx,
                               const float* __restrict__ feat,
                               int2* __restrict__ sidx,
                               float* __restrict__ sfeat,
                               int nedges)
{
    int e = blockIdx.x * 256 + threadIdx.x;
    if (e >= nedges) return;
    int dst = idx[2 * e], src = idx[2 * e + 1];
    int p = atomicAdd(&g_cur[TYPE * 256 + (src >> 7)], 1);
    sidx[p] = make_int2(dst, src);
    const float4* f4 = reinterpret_cast<const float4*>(feat + (size_t)e * KF);
    float4* o4 = reinterpret_cast<float4*>(sfeat + (size_t)p * KF);
#pragma unroll
    for (int q = 0; q < KF / 4; ++q) o4[q] = f4[q];
}

// ---------------------------------------------------------------------------
__global__ void prep_x_kernel(const float* __restrict__ X,
                              u32* __restrict__ Xint,
                              float* __restrict__ zero_out, int natoms)
{
    int idx = blockIdx.x * 256 + threadIdx.x;
    if (idx >= natoms * 32) return;
    int v = idx >> 5, q = idx & 31;
    float2 x = *reinterpret_cast<const float2*>(X + (size_t)v * 64 + q * 2);
    *reinterpret_cast<uint2*>(&Xint[(size_t)v * 64 + q * 2]) = split_pair(x.x, x.y);
    if (zero_out)
        *reinterpret_cast<float2*>(zero_out + (size_t)v * 64 + q * 2) =
            make_float2(0.f, 0.f);
}

// ---------------------------------------------------------------------------
// transform (R11 core): block = 128 atoms x ONE 64-col tile, 8 warps.
// tiles >= xsplit read Xint2 (used by the merged gi/gh launch).
// ---------------------------------------------------------------------------
#define SMEM_U32 (128 * 72 + 64 * 72)   // 13824 u32 = 55296 B

template <bool TRANS>
__global__ void __launch_bounds__(256)
transform_mma_kernel(const u32* __restrict__ Xint,
                     const u32* __restrict__ Xint2, int xsplit,
                     const u32* __restrict__ Wint,
                     int wrow0,
                     void* __restrict__ Tout, int tpitch,
                     const float* __restrict__ bias,
                     int natoms)
{
    extern __shared__ u32 sm[];
    u32* As = sm;                  // [128][72]
    u32* Bs = As + 128 * 72;       // [64][72]

    const int tid  = threadIdx.x;
    const int a0   = blockIdx.x * 128;
    const int tile = blockIdx.y;
    const int c0   = tile * 64;

    {
        const u32* Xsel = (tile >= xsplit) ? Xint2 : Xint;
        const uint4* Xi4 = reinterpret_cast<const uint4*>(Xsel);
        const uint4 z4 = make_uint4(0, 0, 0, 0);
        for (int idx = tid; idx < 128 * 16; idx += 256) {
            int r = idx >> 4, q4 = idx & 15;
            int v = a0 + r;
            uint4 val = (v < natoms) ? Xi4[(size_t)v * 16 + q4] : z4;
            *reinterpret_cast<uint4*>(&As[r * 72 + q4 * 4]) = val;
        }
    }
    {
        const uint4* Wi4 = reinterpret_cast<const uint4*>(Wint) + (size_t)(wrow0 + c0) * 16;
        for (int idx = tid; idx < 64 * 16; idx += 256) {
            int r = idx >> 4, q4 = idx & 15;
            *reinterpret_cast<uint4*>(&Bs[r * 72 + q4 * 4]) = Wi4[r * 16 + q4];
        }
    }
    __syncthreads();

    const int wid = tid >> 5, lane = tid & 31;
    const int g = lane >> 2, t = lane & 3;
    const int mo = wid * 16;
    const int v1 = a0 + mo + g, v2 = v1 + 8;

    float acc[8][4];
#pragma unroll
    for (int nt = 0; nt < 8; ++nt) {
        acc[nt][0] = 0.f; acc[nt][1] = 0.f; acc[nt][2] = 0.f; acc[nt][3] = 0.f;
    }

#pragma unroll
    for (int ks = 0; ks < 4; ++ks) {
        const int kc = ks * 16 + 2 * t;
        uint2 p0 = *reinterpret_cast<const uint2*>(&As[(mo + g)     * 72 + kc]);
        uint2 p1 = *reinterpret_cast<const uint2*>(&As[(mo + g + 8) * 72 + kc]);
        uint2 p2 = *reinterpret_cast<const uint2*>(&As[(mo + g)     * 72 + kc + 8]);
        uint2 p3 = *reinterpret_cast<const uint2*>(&As[(mo + g + 8) * 72 + kc + 8]);
#pragma unroll
        for (int nt = 0; nt < 8; ++nt) {
            const int br = nt * 8 + g;
            uint2 q0 = *reinterpret_cast<const uint2*>(&Bs[br * 72 + kc]);
            uint2 q1 = *reinterpret_cast<const uint2*>(&Bs[br * 72 + kc + 8]);
            mma16816(acc[nt], p0.x, p1.x, p2.x, p3.x, q0.x, q1.x);  // hi*hi
            mma16816(acc[nt], p0.x, p1.x, p2.x, p3.x, q0.y, q1.y);  // hi*lo
            mma16816(acc[nt], p0.y, p1.y, p2.y, p3.y, q0.x, q1.x);  // lo*hi
        }
    }

    if (TRANS) {
        float* T = reinterpret_cast<float*>(Tout);
#pragma unroll
        for (int nt = 0; nt < 8; ++nt) {
            int c = c0 + nt * 8 + 2 * t;
            float b0 = bias[c], b1 = bias[c + 1];
            if (v1 < natoms) {
                T[(size_t)c * natoms + v1]       = acc[nt][0] + b0;
                T[(size_t)(c + 1) * natoms + v1] = acc[nt][1] + b1;
            }
            if (v2 < natoms) {
                T[(size_t)c * natoms + v2]       = acc[nt][2] + b0;
                T[(size_t)(c + 1) * natoms + v2] = acc[nt][3] + b1;
            }
        }
    } else {
        __half* T = reinterpret_cast<__half*>(Tout);
#pragma unroll
        for (int nt = 0; nt < 8; ++nt) {
            int c = c0 + nt * 8 + 2 * t;
            if (v1 < natoms)
                *reinterpret_cast<__half2*>(T + (size_t)v1 * tpitch + c) =
                    __float22half2_rn(make_float2(acc[nt][0], acc[nt][1]));
            if (v2 < natoms)
                *reinterpret_cast<__half2*>(T + (size_t)v2 * tpitch + c) =
                    __float22half2_rn(make_float2(acc[nt][2], acc[nt][3]));
        }
    }
}

// ---------------------------------------------------------------------------
// scatter over SORTED edges: 16 lanes/edge, 16 edges/block.
// ---------------------------------------------------------------------------
template <int KF>
__global__ void __launch_bounds__(256)
scatter_kernel(const __half* __restrict__ T, int tpitch,
               const float* __restrict__ feat,
               const int2*  __restrict__ sidx,
               float*       __restrict__ out,
               int nedges)
{
    const int tid = threadIdx.x;
    const int g = tid >> 4, i4 = tid & 15;
    const int e = blockIdx.x * 16 + g;
    if (e >= nedges) return;

    const int2 ds = __ldg(&sidx[e]);
    const int dst = ds.x, src = ds.y;
    const uint2* trow =
        reinterpret_cast<const uint2*>(T + (size_t)src * tpitch) + i4;

    float f[KF];
    const float4* fp4 = reinterpret_cast<const float4*>(feat + (size_t)e * KF);
#pragma unroll
    for (int q = 0; q < KF / 4; ++q) {
        float4 ff = __ldg(&fp4[q]);
        f[4 * q] = ff.x; f[4 * q + 1] = ff.y; f[4 * q + 2] = ff.z; f[4 * q + 3] = ff.w;
    }

    uint2 bt = __ldg(&trow[KF * 16]);   // bias column group, weight 1
    float2 b01 = __half22float2(*reinterpret_cast<__half2*>(&bt.x));
    float2 b23 = __half22float2(*reinterpret_cast<__half2*>(&bt.y));
    float m0 = b01.x, m1 = b01.y, m2 = b23.x, m3 = b23.y;
#pragma unroll
    for (int kk = 0; kk < KF; ++kk) {
        uint2 tv = __ldg(&trow[kk * 16]);
        float2 t01 = __half22float2(*reinterpret_cast<__half2*>(&tv.x));
        float2 t23 = __half22float2(*reinterpret_cast<__half2*>(&tv.y));
        m0 = fmaf(f[kk], t01.x, m0);
        m1 = fmaf(f[kk], t01.y, m1);
        m2 = fmaf(f[kk], t23.x, m2);
        m3 = fmaf(f[kk], t23.y, m3);
    }

    float* o = out + (size_t)dst * 64 + 4 * i4;
    atomicAdd(o + 0, m0);
    atomicAdd(o + 1, m1);
    atomicAdd(o + 2, m2);
    atomicAdd(o + 3, m3);
}

// ---------------------------------------------------------------------------
// gate kernel: gi/gh rows in G [384][N] (bias included).
// Fuses: split(h') -> XintH, zero next bonds accumulator.
// ---------------------------------------------------------------------------
__global__ void __launch_bounds__(128)
gru_gate_kernel(const float* __restrict__ hprev,
                const float* __restrict__ G,
                float* __restrict__ hout,
                u32* __restrict__ xint_out,
                float* __restrict__ zero_out,
                int natoms)
{
    __shared__ float Xs[128 * 65];
    const int tid = threadIdx.x;
    const int a0  = blockIdx.x * 128;

    for (int idx = tid; idx < 128 * 64; idx += 128) {
        int r = idx >> 6, j = idx & 63;
        int v = a0 + r;
        Xs[r * 65 + j] = (v < natoms) ? hprev[(size_t)v * 64 + j] : 0.f;
    }
    __syncthreads();

    const int v  = a0 + tid;
    const int vv = (v < natoms) ? v : 0;

#pragma unroll 4
    for (int i = 0; i < 64; ++i) {
        float gir = G[(size_t)i         * natoms + vv];
        float giz = G[(size_t)(64 + i)  * natoms + vv];
        float gin = G[(size_t)(128 + i) * natoms + vv];
        float ghr = G[(size_t)(192 + i) * natoms + vv];
        float ghz = G[(size_t)(256 + i) * natoms + vv];
        float ghn = G[(size_t)(320 + i) * natoms + vv];

        float r_ = 1.f / (1.f + __expf(-(gir + ghr)));
        float z_ = 1.f / (1.f + __expf(-(giz + ghz)));
        float n_ = tanhf(gin + r_ * ghn);
        Xs[tid * 65 + i] = (1.f - z_) * n_ + z_ * Xs[tid * 65 + i];
    }
    __syncthreads();

    for (int idx = tid; idx < 128 * 64; idx += 128) {
        int r = idx >> 6, j = idx & 63;
        int v2 = a0 + r;
        if (v2 < natoms) hout[(size_t)v2 * 64 + j] = Xs[r * 65 + j];
    }
    if (xint_out) {
        for (int idx = tid; idx < 128 * 32; idx += 128) {
            int r = idx >> 5, q = idx & 31;
            int v2 = a0 + r;
            if (v2 < natoms) {
                float a = Xs[r * 65 + 2 * q], b = Xs[r * 65 + 2 * q + 1];
                *reinterpret_cast<uint2*>(&xint_out[(size_t)v2 * 64 + q * 2]) =
                    split_pair(a, b);
                *reinterpret_cast<float2*>(zero_out + (size_t)v2 * 64 + q * 2) =
                    make_float2(0.f, 0.f);
            }
        }
    }
}

// ---------------------------------------------------------------------------
extern "C" void kernel_launch(void* const* d_in, const int* in_sizes, int n_in,
                              void* d_out, int out_size)
{
    const float* atom  = (const float*)d_in[0];
    const float* bf    = (const float*)d_in[1];
    const int*   bidx  = (const int*)  d_in[2];
    const float* anf   = (const float*)d_in[3];
    const int*   anidx = (const int*)  d_in[4];
    const float* dif   = (const float*)d_in[5];
    const int*   diidx = (const int*)  d_in[6];
    const float* We    = (const float*)d_in[7];
    const float* be    = (const float*)d_in[8];
    const float* Wa    = (const float*)d_in[9];
    const float* ba    = (const float*)d_in[10];
    const float* Wd    = (const float*)d_in[11];
    const float* bd    = (const float*)d_in[12];
    const float* wi    = (const float*)d_in[13];
    const float* wh    = (const float*)d_in[14];
    const float* bi    = (const float*)d_in[15];
    const float* bh    = (const float*)d_in[16];
    float* out = (float*)d_out;

    const int natoms = in_sizes[0] / 64;
    const int nb = in_sizes[2] / 2;
    const int na = in_sizes[4] / 2;
    const int nd = in_sizes[6] / 2;

    float *pH, *pA, *pB, *pG;
    __half* pT;
    u32 *pWint, *pXint, *pXintH;
    float *pBias, *pFB, *pFA, *pFD;
    int2 *pEB, *pEA, *pED;
    cudaGetSymbolAddress((void**)&pH,     g_h);
    cudaGetSymbolAddress((void**)&pA,     g_a);
    cudaGetSymbolAddress((void**)&pB,     g_b);
    cudaGetSymbolAddress((void**)&pT,     g_T16);
    cudaGetSymbolAddress((void**)&pG,     g_G);
    cudaGetSymbolAddress((void**)&pWint,  g_Wint);
    cudaGetSymbolAddress((void**)&pXint,  g_Xint);
    cudaGetSymbolAddress((void**)&pXintH, g_XintH);
    cudaGetSymbolAddress((void**)&pBias,  g_bias);
    cudaGetSymbolAddress((void**)&pEB,    g_eb);
    cudaGetSymbolAddress((void**)&pEA,    g_ea);
    cudaGetSymbolAddress((void**)&pED,    g_ed);
    cudaGetSymbolAddress((void**)&pFB,    g_fb);
    cudaGetSymbolAddress((void**)&pFA,    g_fa);
    cudaGetSymbolAddress((void**)&pFD,    g_fd);

    cudaFuncSetAttribute(transform_mma_kernel<false>,
                         cudaFuncAttributeMaxDynamicSharedMemorySize, SMEM_U32 * 4);
    cudaFuncSetAttribute(transform_mma_kernel<true>,
                         cudaFuncAttributeMaxDynamicSharedMemorySize, SMEM_U32 * 4);

    const int abk = (natoms + 127) / 128;
    const int xg  = (natoms * 32 + 255) / 256;

    // ---- once per call: weights, combined bias, edge sort, h split ----
    prep_weights_kernel<<<(WTAB_ROWS * 32 + 255) / 256, 256>>>(
        We, be, Wa, ba, Wd, bd, wi, wh, bi, bh);
    hist_kernel<<<(nb + na + nd + 255) / 256, 256>>>(bidx, nb, anidx, na, diidx, nd);
    scan_kernel<<<1, 768>>>();
    permute_kernel<16, 0><<<(nb + 255) / 256, 256>>>(bidx,  bf,  pEB, pFB, nb);
    permute_kernel<8,  1><<<(na + 255) / 256, 256>>>(anidx, anf, pEA, pFA, na);
    permute_kernel<12, 2><<<(nd + 255) / 256, 256>>>(diidx, dif, pED, pFD, nd);
    prep_x_kernel<<<xg, 256>>>(atom, pXintH, pA, natoms);  // split(h0), zero pA

    for (int s = 0; s < 4; ++s) {
        const float* hx = (s == 0) ? atom : pH;

        // ---- bonds: 17 tiles (rows 0..1087), X = split(h); accumulate pA ----
        transform_mma_kernel<false><<<dim3(abk, 17), 256, SMEM_U32 * 4>>>(
            pXintH, nullptr, 1 << 30, pWint, 0, pT, 1088, nullptr, natoms);
        scatter_kernel<16><<<(nb + 15) / 16, 256>>>(pT, 1088, pFB, pEB, pA, nb);

        // ---- angles: 9 tiles (rows 1088..1663); accumulate pB ----
        prep_x_kernel<<<xg, 256>>>(pA, pXint, pB, natoms);
        transform_mma_kernel<false><<<dim3(abk, 9), 256, SMEM_U32 * 4>>>(
            pXint, nullptr, 1 << 30, pWint, 1088, pT, 576, nullptr, natoms);
        scatter_kernel<8><<<(na + 15) / 16, 256>>>(pT, 576, pFA, pEA, pB, na);

        // ---- dihedrals: 13 tiles (rows 1664..2495); accumulate pA ----
        prep_x_kernel<<<xg, 256>>>(pB, pXint, pA, natoms);
        transform_mma_kernel<false><<<dim3(abk, 13), 256, SMEM_U32 * 4>>>(
            pXint, nullptr, 1 << 30, pWint, 1664, pT, 832, nullptr, natoms);
        scatter_kernel<12><<<(nd + 15) / 16, 256>>>(pT, 832, pFD, pED, pA, nd);

        // ---- GRU: merged gi(tiles 0-2, X=a-split) + gh(tiles 3-5, X=h-split) ----
        prep_x_kernel<<<xg, 256>>>(pA, pXint, nullptr, natoms);
        transform_mma_kernel<true><<<dim3(abk, 6), 256, SMEM_U32 * 4>>>(
            pXint, pXintH, 3, pWint, 2496, pG, 0, pBias, natoms);
        const bool last = (s == 3);
        gru_gate_kernel<<<abk, 128>>>(
            hx, pG,
            last ? out : pH,
            last ? nullptr : pXintH,   // split(h') for next bonds + next gh
            last ? nullptr : pA,       // zero next bonds accumulator
            natoms);
    }
}